// round 16
// baseline (speedup 1.0000x reference)
#include <cuda_runtime.h>
#include <stdint.h>
#include <math.h>

#define FMASK 0xffffffffu

static __device__ __forceinline__ float ex2f(float x){ float y; asm("ex2.approx.f32 %0, %1;" : "=f"(y) : "f"(x)); return y; }
static __device__ __forceinline__ float lg2f(float x){ float y; asm("lg2.approx.f32 %0, %1;" : "=f"(y) : "f"(x)); return y; }
static __device__ __forceinline__ float rcpf(float x){ float y; asm("rcp.approx.f32 %0, %1;" : "=f"(y) : "f"(x)); return y; }
static __device__ __forceinline__ void cp16(uint32_t dst, const void* src){
    asm volatile("cp.async.cg.shared.global [%0], [%1], 16;" :: "r"(dst), "l"(src) : "memory");
}
static __device__ __forceinline__ void cpcommit(){ asm volatile("cp.async.commit_group;" ::: "memory"); }
static __device__ __forceinline__ void cpwait14(){ asm volatile("cp.async.wait_group 14;" ::: "memory"); }

static __device__ __forceinline__ int ld_acq(const int* p){
    int v; asm volatile("ld.acquire.gpu.b32 %0, [%1];" : "=r"(v) : "l"(p) : "memory"); return v;
}
static __device__ __forceinline__ void st_rel(int* p, int v){
    asm volatile("st.release.gpu.b32 [%0], %1;" :: "l"(p), "r"(v) : "memory");
}

// packed f32x2 helpers
union F2 { unsigned long long u; float f[2]; };
static __device__ __forceinline__ unsigned long long dup2(float x){
    unsigned long long r; asm("mov.b64 %0, {%1, %1};" : "=l"(r) : "f"(x)); return r;
}
static __device__ __forceinline__ unsigned long long pk2(float lo, float hi){
    unsigned long long r; asm("mov.b64 %0, {%1, %2};" : "=l"(r) : "f"(lo), "f"(hi)); return r;
}
static __device__ __forceinline__ unsigned long long fma2(unsigned long long a, unsigned long long b, unsigned long long c){
    unsigned long long d; asm("fma.rn.f32x2 %0, %1, %2, %3;" : "=l"(d) : "l"(a), "l"(b), "l"(c)); return d;
}
static __device__ __forceinline__ unsigned long long add2(unsigned long long a, unsigned long long b){
    unsigned long long d; asm("add.rn.f32x2 %0, %1, %2;" : "=l"(d) : "l"(a), "l"(b)); return d;
}
static __device__ __forceinline__ unsigned long long mul2(unsigned long long a, unsigned long long b){
    unsigned long long d; asm("mul.rn.f32x2 %0, %1, %2;" : "=l"(d) : "l"(a), "l"(b)); return d;
}
static __device__ __forceinline__ float2 unpk2(unsigned long long v){
    float2 f; asm("mov.b64 {%0, %1}, %2;" : "=f"(f.x), "=f"(f.y) : "l"(v)); return f;
}

// Scratch (allocation-free __device__ globals)
__device__ float g_e[128*1024*16];   // unnormalized softmax numerators e_t
__device__ float g_u[128*1024*16];   // raw mixed logits u_t (l_t = u_t * r_{t-1})
__device__ float g_r[128*1024];      // r_t = 1/S_t  (y_t = e_t * r_t)
__device__ int   g_flag[128*16];     // per (b, 64-step tile) release flags

__global__ void reset_kernel() {
    const int i = blockIdx.x * 1024 + threadIdx.x;
    if (i < 128*16) g_flag[i] = 0;
}

// ============================================================================
// Fused kernel. Region by blockIdx.x:
//   [0, 128)        : scan  (warp 0 of CTA; warp 1 writes C_seq)
//   [128, 2176)     : expansion tiles (b = (bid-128)>>4, tile = (bid-128)&15)
//   [2176, 2518)    : scalars (lq/lp), 384 t's per CTA
// Publication: ALL scan lanes __threadfence(), __syncwarp(), then lane 0
// st.release — orders every lane's STGs before the flag (release alone only
// covers the releasing thread's stores).
// ============================================================================
__global__ __launch_bounds__(384, 1)
void fused_kernel(const float* __restrict__ logits,
                  const float* __restrict__ gum,
                  const float* __restrict__ Amat,
                  const float* __restrict__ Bmat,
                  const float* __restrict__ Cmat,
                  const float* __restrict__ transP,
                  float* __restrict__ out)
{
    constexpr int T = 1024;
    constexpr float SCALE = 2.8853900817779268f;   // (1/tau)*log2(e), tau = 0.5
    constexpr float LOG2E = 1.4426950408889634f;
    constexpr float LN2   = 0.6931471805599453f;

    __shared__ __align__(16) float ring[16*256];   // scan: logits ring
    __shared__ __align__(16) float gring[16*16];   // scan: gumbel ring
    __shared__ __align__(8)  float ebc[16];        // scan: e broadcast
    __shared__ __align__(16) float es[64*16];      // expand: staged e tile
    __shared__ float rs[64];                       // expand: staged r tile
    __shared__ __align__(16) float lgP[256];       // scalars: log(transP)

    const int bid = blockIdx.x;
    const int tid = threadIdx.x;

    float* outA  = out;                 // (B,T,16,16)
    float* outB  = out + 33554432u;     // (B,T,16,8)
    float* outC  = out + 50331648u;     // (B,1,32,16)
    float* outLq = out + 50397184u;     // (B,T)
    float* outLp = out + 50528256u;     // (B,T)

    if (bid < 128) {
        // ================= SCAN region =================
        const int b = bid;
        if (tid >= 64) return;
        if (tid >= 32) {
            // warp 1: C_seq broadcast for this row
            const float4* c4 = reinterpret_cast<const float4*>(Cmat);
            float4* o4 = reinterpret_cast<float4*>(outC + b*512);
            #pragma unroll
            for (int i = tid - 32; i < 128; i += 32) o4[i] = c4[i];
            return;
        }
        const int lane = tid;
        const int j = lane & 15;

        const float* Lrow = logits + (size_t)b * ((size_t)T * 256);
        const float* grow = gum    + (size_t)b * ((size_t)T * 16);
        float* pe = g_e + (size_t)b * (T * 16) + j;
        float* pu = g_u + (size_t)b * (T * 16) + j;
        float* pr = g_r + (size_t)b * T;
        int* flags = g_flag + b*16;
        uint32_t ring_b  = (uint32_t)__cvta_generic_to_shared(ring);
        uint32_t gring_b = (uint32_t)__cvta_generic_to_shared(gring);

        ebc[j] = 1.0f;
        #pragma unroll
        for (int pt = 0; pt < 15; ++pt) {
            uint32_t sb = ring_b + pt*1024 + lane*16;
            const float* gp = Lrow + (size_t)pt*256 + lane*4;
            cp16(sb, gp);
            cp16(sb + 512, gp + 128);
            if (lane < 4) cp16(gring_b + pt*64 + lane*16, grow + (size_t)pt*16 + lane*4);
            cpcommit();
        }

        const float* gq = grow + (size_t)(lane & 3) * 4;

        for (int h = 0; h < 16; ++h) {          // 16 tiles of 64 steps
            const int tbase = h * 64;
            #pragma unroll 4
            for (int s = 0; s < 64; ++s) {
                const int t = tbase + s;
                {
                    const int ft = (t + 15 < T) ? (t + 15) : (T - 1);
                    uint32_t sb = ring_b + ((t + 15) & 15)*1024 + lane*16;
                    const float* gp = Lrow + (size_t)ft*256 + lane*4;
                    cp16(sb, gp);
                    cp16(sb + 512, gp + 128);
                    if (lane < 4) cp16(gring_b + ((t + 15) & 15)*64 + lane*16, gq + (size_t)ft*16);
                    cpcommit();
                }
                cpwait14();
                __syncwarp();

                F2 E[8];
                {
                    const float2* eb2 = reinterpret_cast<const float2*>(ebc);
                    #pragma unroll
                    for (int m = 0; m < 8; ++m) { const float2 v = eb2[m]; E[m].f[0] = v.x; E[m].f[1] = v.y; }
                }

                const float* rb = ring + (t & 15)*256;
                float Lc[16];
                #pragma unroll
                for (int k = 0; k < 16; ++k) Lc[k] = rb[k*16 + j];
                const float gC = gring[(t & 15)*16 + j] * SCALE;

                unsigned long long s0 = add2(E[0].u, E[1].u);
                unsigned long long s1 = add2(E[2].u, E[3].u);
                unsigned long long s2 = add2(E[4].u, E[5].u);
                unsigned long long s3 = add2(E[6].u, E[7].u);
                s0 = add2(s0, s1); s2 = add2(s2, s3); s0 = add2(s0, s2);
                F2 fs; fs.u = s0;
                const float S = fs.f[0] + fs.f[1];
                const float r = rcpf(S);
                const float rC = r * SCALE;
                const int tprev = (t > 0) ? (t - 1) : 0;
                if (lane == 0) pr[tprev] = r;

                float u0 = E[0].f[0]*Lc[0],  u1 = E[0].f[1]*Lc[1];
                float u2 = E[1].f[0]*Lc[2],  u3 = E[1].f[1]*Lc[3];
                u0 = fmaf(E[2].f[0], Lc[4],  u0); u1 = fmaf(E[2].f[1], Lc[5],  u1);
                u2 = fmaf(E[3].f[0], Lc[6],  u2); u3 = fmaf(E[3].f[1], Lc[7],  u3);
                u0 = fmaf(E[4].f[0], Lc[8],  u0); u1 = fmaf(E[4].f[1], Lc[9],  u1);
                u2 = fmaf(E[5].f[0], Lc[10], u2); u3 = fmaf(E[5].f[1], Lc[11], u3);
                u0 = fmaf(E[6].f[0], Lc[12], u0); u1 = fmaf(E[6].f[1], Lc[13], u1);
                u2 = fmaf(E[7].f[0], Lc[14], u2); u3 = fmaf(E[7].f[1], Lc[15], u3);
                const float u = (u0 + u1) + (u2 + u3);

                const float x = fmaf(u, rC, gC);
                const float en = ex2f(x);

                ebc[j] = en;
                pe[(size_t)t*16] = en;
                pu[(size_t)t*16] = u;
            }
            // ---- publish tile h-1 (pe/pu[0..tbase+63], pr[0..tbase+62] done;
            //      tile h-1 needs pr up to 64h-1 = tbase-1 ✓) ----
            if (h > 0) {
                __threadfence();                 // every lane orders its own STGs
                __syncwarp();
                if (lane == 0) st_rel(&flags[h - 1], 1);
            }
        }

        // epilogue: r_{1023}, publish tiles 14 and 15
        __syncwarp();
        if (lane == 0) {
            float S = 0.0f;
            #pragma unroll
            for (int k = 0; k < 16; ++k) S += ebc[k];
            pr[T - 1] = rcpf(S);
        }
        __threadfence();
        __syncwarp();
        if (lane == 0) { st_rel(&flags[14], 1); st_rel(&flags[15], 1); }
    } else if (bid < 2176) {
        // ================= EXPANSION region =================
        const int q2 = bid - 128;
        const int b = q2 >> 4;
        const int tile = q2 & 15;
        const int t0 = tile * 64;
        const int tsub = tid / 96;
        const int e96 = tid % 96;

        unsigned long long M[32];
        const float* Msrc;
        int stride, base;
        if (e96 < 64) { const int i = e96 >> 2, jc = (e96 & 3) * 4; base = i*16 + jc; stride = 256; Msrc = Amat; }
        else          { const int q = e96 - 64; const int i = q >> 1, jc = (q & 1) * 4; base = i*8 + jc; stride = 128; Msrc = Bmat; }
        #pragma unroll
        for (int k = 0; k < 16; ++k) {
            const float4 v = *reinterpret_cast<const float4*>(Msrc + k*stride + base);
            M[2*k]   = pk2(v.x, v.y);
            M[2*k+1] = pk2(v.z, v.w);
        }

        if (tid == 0) { while (ld_acq(&g_flag[b*16 + tile]) == 0) __nanosleep(256); }
        __syncthreads();

        const float* esrc = g_e + ((size_t)b*1024 + t0) * 16;
        if (tid < 256) *reinterpret_cast<float4*>(&es[tid*4]) = *reinterpret_cast<const float4*>(&esrc[tid*4]);
        if (tid >= 320) rs[tid - 320] = g_r[(size_t)b*1024 + t0 + (tid - 320)];
        __syncthreads();

        float* outp = ((e96 < 64) ? outA : outB) + ((size_t)b*1024 + t0) * (size_t)stride + base;

        #pragma unroll 4
        for (int tt = 0; tt < 16; ++tt) {
            const int tl = tt*4 + tsub;
            const float4* ep4 = reinterpret_cast<const float4*>(&es[tl*16]);
            const float4 y0 = ep4[0], y1 = ep4[1], y2 = ep4[2], y3 = ep4[3];
            unsigned long long d[16];
            d[0]=dup2(y0.x); d[1]=dup2(y0.y); d[2]=dup2(y0.z); d[3]=dup2(y0.w);
            d[4]=dup2(y1.x); d[5]=dup2(y1.y); d[6]=dup2(y1.z); d[7]=dup2(y1.w);
            d[8]=dup2(y2.x); d[9]=dup2(y2.y); d[10]=dup2(y2.z); d[11]=dup2(y2.w);
            d[12]=dup2(y3.x); d[13]=dup2(y3.y); d[14]=dup2(y3.z); d[15]=dup2(y3.w);
            unsigned long long a0 = mul2(d[0], M[0]);
            unsigned long long a1 = mul2(d[0], M[1]);
            #pragma unroll
            for (int k = 1; k < 16; ++k) {
                a0 = fma2(d[k], M[2*k],   a0);
                a1 = fma2(d[k], M[2*k+1], a1);
            }
            const unsigned long long rd = dup2(rs[tl]);
            a0 = mul2(a0, rd);
            a1 = mul2(a1, rd);
            const float2 f0 = unpk2(a0), f1 = unpk2(a1);
            *reinterpret_cast<float4*>(outp + (size_t)tl * stride) = make_float4(f0.x, f0.y, f1.x, f1.y);
        }
    } else {
        // ================= SCALARS region =================
        if (tid < 256) lgP[tid] = logf(transP[tid]);
        __syncthreads();

        const int idx = (bid - 2176) * 384 + tid;
        if (idx >= 128*1024) return;
        const int b = idx >> 10;
        const int t = idx & 1023;

        { // per-thread acquire spin on own tile's flag
            const int* fp = &g_flag[b*16 + (t >> 6)];
            while (ld_acq(fp) == 0) __nanosleep(256);
        }

        const size_t bt = (size_t)b*1024 + t;
        float esv[16], us[16], ep[16];
        {
            const float4* e4 = reinterpret_cast<const float4*>(g_e + bt*16);
            const float4* u4 = reinterpret_cast<const float4*>(g_u + bt*16);
            #pragma unroll
            for (int q = 0; q < 4; ++q) {
                const float4 ev = e4[q], uv = u4[q];
                esv[q*4+0]=ev.x; esv[q*4+1]=ev.y; esv[q*4+2]=ev.z; esv[q*4+3]=ev.w;
                us[q*4+0]=uv.x; us[q*4+1]=uv.y; us[q*4+2]=uv.z; us[q*4+3]=uv.w;
            }
        }
        const float rt = g_r[bt];
        float rm;
        if (t == 0) {
            rm = 0.0625f;
            #pragma unroll
            for (int k = 0; k < 16; ++k) ep[k] = 1.0f;
        } else {
            rm = g_r[bt - 1];
            const float4* p4 = reinterpret_cast<const float4*>(g_e + (bt - 1)*16);
            #pragma unroll
            for (int q = 0; q < 4; ++q) {
                const float4 pv = p4[q];
                ep[q*4+0]=pv.x; ep[q*4+1]=pv.y; ep[q*4+2]=pv.z; ep[q*4+3]=pv.w;
            }
        }

        float yj[16], lj[16];
        float dd = 0.0f, ee = 0.0f;
        #pragma unroll
        for (int k = 0; k < 16; ++k) {
            yj[k] = esv[k] * rt;
            lj[k] = us[k] * rm;
            dd = fmaf(yj[k], lj[k], dd);
            ee += ex2f(lj[k] * LOG2E);
        }
        const float lq = dd - lg2f(ee) * LN2;

        const float4* P4 = reinterpret_cast<const float4*>(lgP);
        float acc = 0.0f;
        #pragma unroll
        for (int i = 0; i < 16; ++i) {
            const float4 r0 = P4[i*4+0], r1 = P4[i*4+1], r2 = P4[i*4+2], r3 = P4[i*4+3];
            float wv =        yj[0]*r0.x;
            wv = fmaf(yj[1],  r0.y, wv); wv = fmaf(yj[2],  r0.z, wv); wv = fmaf(yj[3],  r0.w, wv);
            wv = fmaf(yj[4],  r1.x, wv); wv = fmaf(yj[5],  r1.y, wv); wv = fmaf(yj[6],  r1.z, wv);
            wv = fmaf(yj[7],  r1.w, wv); wv = fmaf(yj[8],  r2.x, wv); wv = fmaf(yj[9],  r2.y, wv);
            wv = fmaf(yj[10], r2.z, wv); wv = fmaf(yj[11], r2.w, wv); wv = fmaf(yj[12], r3.x, wv);
            wv = fmaf(yj[13], r3.y, wv); wv = fmaf(yj[14], r3.z, wv); wv = fmaf(yj[15], r3.w, wv);
            acc = fmaf(ep[i] * rm, wv, acc);
        }
        const float lp = (t == 0) ? -2.7725887222397811f : acc;   // -log(16) at t=0

        outLq[bt] = lq;
        outLp[bt] = lp;
    }
}

extern "C" void kernel_launch(void* const* d_in, const int* in_sizes, int n_in,
                              void* d_out, int out_size)
{
    const float *logits = nullptr, *gum = nullptr, *A = nullptr, *Bm = nullptr,
                *Cm = nullptr, *tP = nullptr;
    for (int i = 0; i < n_in; ++i) {
        switch (in_sizes[i]) {
            case 33554432: logits = (const float*)d_in[i]; break;  // (128,1024,16,16)
            case 2097152:  gum    = (const float*)d_in[i]; break;  // (128,1024,16)
            case 4096:     A      = (const float*)d_in[i]; break;  // (16,16,16)
            case 2048:     Bm     = (const float*)d_in[i]; break;  // (16,16,8)
            case 8192:     Cm     = (const float*)d_in[i]; break;  // (16,32,16)
            case 256:      tP     = (const float*)d_in[i]; break;  // (16,16)
        }
    }
    (void)out_size;
    reset_kernel<<<2, 1024>>>();
    fused_kernel<<<2518, 384>>>(logits, gum, A, Bm, Cm, tP, (float*)d_out);
}